// round 14
// baseline (speedup 1.0000x reference)
#include <cuda_runtime.h>
#include <cstdint>

#define NN 4096
#define DD 512
#define FF 512
#define HH 4
#define KK 1024
#define ALPHA 0.3f
#define L2E 1.4426950408889634f
#define ST 36        // padded smem row stride (floats)

// ---- scratch (device globals; no allocation allowed) ----
__device__ float g_A[NN * KK];          // tf32-rounded [nodes | edges+labels], [m][k]
__device__ float g_BT[HH * FF * KK];    // tf32-rounded [h][f][k] = [W^T | We^T]
__device__ float g_bias2[HH * FF];
__device__ float g_featsT[(size_t)HH * FF * NN];  // [h][f][m], tf32-rounded
__device__ float g_s[HH * NN];
__device__ float g_t[HH * NN];
__device__ float g_rmax[HH * NN];
__device__ float g_invz[HH * NN];
__device__ float g_wu[HH * DD];
__device__ float g_wv[HH * DD];
__device__ float g_bu[HH];
__device__ float g_bv[HH];
__device__ float g_hpmax[HH];
__device__ float g_hmmin[HH];

// ================= helpers =================
__device__ __forceinline__ float warp_sum(float x) {
#pragma unroll
    for (int o = 16; o > 0; o >>= 1) x += __shfl_xor_sync(0xffffffffu, x, o);
    return x;
}
__device__ __forceinline__ uint32_t cvt_tf32(float x) {
    uint32_t r; asm("cvt.rna.tf32.f32 %0, %1;" : "=r"(r) : "f"(x)); return r;
}
__device__ __forceinline__ float tf32r(float x) {
    return __uint_as_float(cvt_tf32(x));
}
__device__ __forceinline__ float fex2(float y) {
    float r; asm("ex2.approx.ftz.f32 %0, %1;" : "=f"(r) : "f"(y)); return r;
}
__device__ __forceinline__ uint32_t smem_u32(const void* p) {
    uint32_t a;
    asm("{ .reg .u64 t; cvta.to.shared.u64 t, %1; cvt.u32.u64 %0, t; }"
        : "=r"(a) : "l"(p));
    return a;
}
__device__ __forceinline__ void cpasync16(uint32_t dst, const void* src) {
    asm volatile("cp.async.cg.shared.global [%0], [%1], 16;" :: "r"(dst), "l"(src));
}
__device__ __forceinline__ void cp_commit() {
    asm volatile("cp.async.commit_group;" ::: "memory");
}
template <int N>
__device__ __forceinline__ void cp_wait() {
    asm volatile("cp.async.wait_group %0;" :: "n"(N) : "memory");
}
__device__ __forceinline__ void mma1688(float* c, const uint32_t* a, uint32_t b0, uint32_t b1) {
    asm volatile(
        "mma.sync.aligned.m16n8k8.row.col.f32.tf32.tf32.f32 "
        "{%0,%1,%2,%3}, {%4,%5,%6,%7}, {%8,%9}, {%0,%1,%2,%3};"
        : "+f"(c[0]), "+f"(c[1]), "+f"(c[2]), "+f"(c[3])
        : "r"(a[0]), "r"(a[1]), "r"(a[2]), "r"(a[3]), "r"(b0), "r"(b1));
}

// ================= fused setup kernel =================
#define SETUP_BLOCKS 4361

__global__ __launch_bounds__(256) void setup_kernel(
    const float* __restrict__ nodes, const float* __restrict__ edges,
    const float* __restrict__ labels, const float* __restrict__ W,
    const float* __restrict__ We, const float* __restrict__ b,
    const float* __restrict__ be, const float* __restrict__ u,
    const float* __restrict__ v)
{
    __shared__ float tile[32][33];
    int bx = blockIdx.x;
    int tid = threadIdx.x;
    if (bx < 2048) {
        int i = bx * 256 + tid;           // float4 index over NN*DD/4
        int m = i >> 7, dq = i & 127;
        float4 a = ((const float4*)nodes)[i];
        float4 x = ((const float4*)edges)[i];
        float4 y = ((const float4*)labels)[i];
        float* h0 = g_A + (size_t)m * KK + dq * 4;
        float av[4] = {a.x, a.y, a.z, a.w};
        float cv[4] = {x.x + y.x, x.y + y.y, x.z + y.z, x.w + y.w};
#pragma unroll
        for (int j = 0; j < 4; j++) {
            h0[j] = tf32r(av[j]);
            h0[DD + j] = tf32r(cv[j]);
        }
    } else if (bx < 4096) {
        int jb = bx - 2048;
        int h = jb >> 9;
        int r = jb & 511;
        int k0 = (r >> 4) * 32, f0 = (r & 15) * 32;
        int tx = tid & 31, ty0 = tid >> 5;
#pragma unroll
        for (int j = 0; j < 4; j++) {
            int ty = ty0 * 4 + j;
            int k = k0 + ty;
            float vv = (k < DD) ? W[((size_t)h * DD + k) * FF + f0 + tx]
                                : We[(size_t)(k - DD) * FF + f0 + tx];
            tile[ty][tx] = vv;
        }
        __syncthreads();
#pragma unroll
        for (int j = 0; j < 4; j++) {
            int ty = ty0 * 4 + j;
            g_BT[((size_t)h * FF + f0 + ty) * KK + k0 + tx] = tf32r(tile[tx][ty]);
        }
    } else if (bx < 4104) {
        int i = (bx - 4096) * 256 + tid;
        int f = i & (FF - 1);
        g_bias2[i] = b[i] + be[f];
    } else if (bx < 4360) {
        int w = (bx - 4104) * 8 + (tid >> 5);
        int lane = tid & 31;
        int h = w / DD, d = w % DD;
        const float4* Wr = (const float4*)(W + ((long)h * DD + d) * FF);
        const float4* up = (const float4*)(u + (long)h * FF);
        const float4* vp = (const float4*)(v + (long)h * FF);
        float su = 0.f, sv = 0.f;
        for (int i = lane; i < FF / 4; i += 32) {
            float4 w4 = Wr[i], u4 = up[i], v4 = vp[i];
            su += w4.x * u4.x + w4.y * u4.y + w4.z * u4.z + w4.w * u4.w;
            sv += w4.x * v4.x + w4.y * v4.y + w4.z * v4.z + w4.w * v4.w;
        }
        su = warp_sum(su); sv = warp_sum(sv);
        if (lane == 0) { g_wu[h * DD + d] = su; g_wv[h * DD + d] = sv; }
    } else {
        if (tid < 128) {
            int h = tid >> 5;
            int lane = tid & 31;
            float su = 0.f, sv = 0.f;
            for (int i = lane; i < FF; i += 32) {
                float bb = b[h * FF + i];
                su += bb * u[h * FF + i];
                sv += bb * v[h * FF + i];
            }
            su = warp_sum(su); sv = warp_sum(sv);
            if (lane == 0) { g_bu[h] = su; g_bv[h] = sv; }
        }
    }
}

// ================= rank-1 precomputation =================
__global__ __launch_bounds__(256) void st_kernel(const float* __restrict__ nodes) {
    int w = blockIdx.x * 8 + (threadIdx.x >> 5);
    int lane = threadIdx.x & 31;
    int h = w >> 12;
    int n = w & (NN - 1);
    const float4* nr = (const float4*)(nodes + (long)n * DD);
    const float4* wu = (const float4*)(g_wu + (long)h * DD);
    const float4* wv = (const float4*)(g_wv + (long)h * DD);
    float ss = 0.f, tt = 0.f;
    for (int i = lane; i < DD / 4; i += 32) {
        float4 x = nr[i], a = wu[i], c = wv[i];
        ss += x.x * a.x + x.y * a.y + x.z * a.z + x.w * a.w;
        tt += x.x * c.x + x.y * c.y + x.z * c.z + x.w * c.w;
    }
    ss = warp_sum(ss); tt = warp_sum(tt);
    if (lane == 0) {
        g_s[h * NN + n] = ss + g_bu[h];
        g_t[h * NN + n] = tt + g_bv[h];
    }
}

__global__ void minmax_kernel() {
    int h = blockIdx.x;
    int tid = threadIdx.x;
    __shared__ float smx[256], smn[256];
    float mx = -1e30f, mn = 1e30f;
    for (int m = tid; m < NN; m += 256) {
        float t = g_t[h * NN + m];
        float hp = t >= 0.f ? t : ALPHA * t;
        float hm = t <= 0.f ? t : ALPHA * t;
        mx = fmaxf(mx, hp);
        mn = fminf(mn, hm);
    }
    smx[tid] = mx; smn[tid] = mn;
    __syncthreads();
    for (int sft = 128; sft > 0; sft >>= 1) {
        if (tid < sft) {
            smx[tid] = fmaxf(smx[tid], smx[tid + sft]);
            smn[tid] = fminf(smn[tid], smn[tid + sft]);
        }
        __syncthreads();
    }
    if (tid == 0) { g_hpmax[h] = smx[0]; g_hmmin[h] = smn[0]; }
}

__global__ __launch_bounds__(256) void z_kernel() {
    int w = blockIdx.x * 8 + (threadIdx.x >> 5);
    int lane = threadIdx.x & 31;
    int h = w >> 12, n = w & (NN - 1);
    float s = g_s[h * NN + n];
    float rmax = s > 0.f ? s * g_hpmax[h] : (s < 0.f ? s * g_hmmin[h] : 0.f);
    const float* tp = g_t + (long)h * NN;
    float z = 0.f;
    for (int m = lane; m < NN; m += 32) {
        float sc = s * tp[m];
        sc = sc >= 0.f ? sc : ALPHA * sc;
        z += fex2(fmaxf((sc - rmax) * L2E, -126.f));
    }
    z = warp_sum(z);
    if (lane == 0) {
        g_rmax[h * NN + n] = rmax;
        g_invz[h * NN + n] = 1.f / z;
    }
}

// ========= feats GEMM: 64x64 warp tiles, in-CTA k-split, 2-stage =========
// CTA 128m x 128f, 8 warps: wq = warp&3 -> 2x2 grid of 64x64 tiles,
// kw = warp>>2 -> k-substeps {2kw, 2kw+1}. End: kw=1 accs merged via smem.
#define F_STG (2 * 128 * ST)       // 9216 floats per stage (A + B)
#define F_SMEM (2 * F_STG * 4)     // 73728 bytes
#define RED_STRIDE 132

__global__ __launch_bounds__(256) void feats_gemm() {
    extern __shared__ float sm[];
    int tid = threadIdx.x, wid = tid >> 5, lane = tid & 31;
    int g = lane >> 2, tg = lane & 3;
    int kw = wid >> 2, wq = wid & 3;
    int warp_m = wq & 1, warp_n = wq >> 1;
    int h = blockIdx.z;
    int m0 = blockIdx.y * 128, f0 = blockIdx.x * 128;
    const float* Bp = g_BT + (size_t)h * FF * KK;

    float acc[4][8][4];
#pragma unroll
    for (int a = 0; a < 4; a++)
#pragma unroll
        for (int bq = 0; bq < 8; bq++)
#pragma unroll
            for (int c = 0; c < 4; c++) acc[a][bq][c] = 0.f;

    int prow = tid & 127, pseg = tid >> 7;

    auto prod = [&](int c, int s) {
        float* As = sm + s * F_STG;
        float* Bs = As + 128 * ST;
        int k0 = c * 32;
        const float* asrc = g_A + (size_t)(m0 + prow) * KK + k0 + pseg * 16;
        const float* bsrc = Bp + (size_t)(f0 + prow) * KK + k0 + pseg * 16;
        uint32_t ad = smem_u32(As + prow * ST + pseg * 16);
        uint32_t bd = smem_u32(Bs + prow * ST + pseg * 16);
#pragma unroll
        for (int j = 0; j < 4; j++) {
            cpasync16(ad + j * 16, asrc + j * 4);
            cpasync16(bd + j * 16, bsrc + j * 4);
        }
    };
    auto domma = [&](int s) {
        float* As = sm + s * F_STG;
        float* Bs = As + 128 * ST;
#pragma unroll
        for (int kk = 0; kk < 2; kk++) {
            int ks = kw * 2 + kk;
            uint32_t a[4][4];
#pragma unroll
            for (int mt = 0; mt < 4; mt++) {
                int base = warp_m * 64 + mt * 16;
                a[mt][0] = __float_as_uint(As[(base + g) * ST + ks * 8 + tg]);
                a[mt][1] = __float_as_uint(As[(base + 8 + g) * ST + ks * 8 + tg]);
                a[mt][2] = __float_as_uint(As[(base + g) * ST + ks * 8 + tg + 4]);
                a[mt][3] = __float_as_uint(As[(base + 8 + g) * ST + ks * 8 + tg + 4]);
            }
#pragma unroll
            for (int nt = 0; nt < 8; nt++) {
                int fc = warp_n * 64 + nt * 8 + g;
                uint32_t b0 = __float_as_uint(Bs[fc * ST + ks * 8 + tg]);
                uint32_t b1 = __float_as_uint(Bs[fc * ST + ks * 8 + tg + 4]);
#pragma unroll
                for (int mt = 0; mt < 4; mt++)
                    mma1688(acc[mt][nt], a[mt], b0, b1);
            }
        }
    };

    const int NIT = KK / 32;   // 32
    prod(0, 0); cp_commit();
    for (int i = 0; i < NIT; i++) {
        cp_wait<0>();
        __syncthreads();
        if (i + 1 < NIT) { prod(i + 1, (i + 1) & 1); cp_commit(); }
        domma(i & 1);
    }

    // merge k-group 1 into k-group 0 via smem
    __syncthreads();
    if (kw == 1) {
        float4* dst = (float4*)&sm[(wq * 32 + lane) * RED_STRIDE];
        const float4* src = (const float4*)&acc[0][0][0];
#pragma unroll
        for (int j = 0; j < 32; j++) dst[j] = src[j];
    }
    __syncthreads();
    if (kw == 0) {
        const float4* src = (const float4*)&sm[(wq * 32 + lane) * RED_STRIDE];
        float* ap = &acc[0][0][0];
#pragma unroll
        for (int j = 0; j < 32; j++) {
            float4 v = src[j];
            ap[j * 4 + 0] += v.x; ap[j * 4 + 1] += v.y;
            ap[j * 4 + 2] += v.z; ap[j * 4 + 3] += v.w;
        }
        float* dst = g_featsT + (size_t)h * FF * NN;
#pragma unroll
        for (int mt = 0; mt < 4; mt++) {
#pragma unroll
            for (int nt = 0; nt < 8; nt++) {
                int row = m0 + warp_m * 64 + mt * 16 + g;
                int col = f0 + warp_n * 64 + nt * 8 + tg * 2;
                float b0v = g_bias2[h * FF + col];
                float b1v = g_bias2[h * FF + col + 1];
                dst[(size_t)col * NN + row]           = tf32r(acc[mt][nt][0] + b0v);
                dst[(size_t)(col + 1) * NN + row]     = tf32r(acc[mt][nt][1] + b1v);
                dst[(size_t)col * NN + row + 8]       = tf32r(acc[mt][nt][2] + b0v);
                dst[(size_t)(col + 1) * NN + row + 8] = tf32r(acc[mt][nt][3] + b1v);
            }
        }
    }
}

// ========= fused attention GEMM: 64x64 warp tiles, in-CTA k-split =========
// CTA 128n x 128f, 256 threads. Grid (4, 32) = 128 CTAs.
// w = 2^( s_n*t_m * (>=0 ? L2E : 0.3*L2E) + C_n ), C_n = log2(invz_n) - rmax_n*L2E
#define A_CONST 1024                // s_sm[512] + c_sm[512]
#define A_STG (2 * 128 * ST)        // 9216 floats (A + B)
#define A_SMEM ((A_CONST + 2 * A_STG) * 4)   // 77824 bytes

__global__ __launch_bounds__(256) void attn_gemm(float* __restrict__ out) {
    extern __shared__ float sm[];
    float* s_sm = sm;              // [4h][128]
    float* c_sm = sm + 512;        // [4h][128]
    int tid = threadIdx.x, wid = tid >> 5, lane = tid & 31;
    int g = lane >> 2, tg = lane & 3;
    int kw = wid >> 2, wq = wid & 3;
    int warp_m = wq & 1, warp_n = wq >> 1;
    int n0 = blockIdx.y * 128, f0 = blockIdx.x * 128;

#pragma unroll
    for (int j = 0; j < 2; j++) {
        int idx = j * 256 + tid;
        int hh = idx >> 7, nl = idx & 127;
        float iz = g_invz[hh * NN + n0 + nl];
        float rm = g_rmax[hh * NN + n0 + nl];
        s_sm[idx] = g_s[hh * NN + n0 + nl];
        c_sm[idx] = __log2f(iz) - rm * L2E;
    }

    float acc[4][8][4];
#pragma unroll
    for (int a = 0; a < 4; a++)
#pragma unroll
        for (int bq = 0; bq < 8; bq++)
#pragma unroll
            for (int c = 0; c < 4; c++) acc[a][bq][c] = 0.f;

    int nloc = tid & 127, kq = tid >> 7;      // weight gen: 16 k's each
    int prow = tid & 127, pseg = tid >> 7;    // B copy

    auto prod = [&](int c, int s) {
        float* As = sm + A_CONST + s * A_STG;
        float* Bs = As + 128 * ST;
        int h = c >> 7;
        int m0 = (c & 127) << 5;
        float sv = s_sm[h * 128 + nloc];
        float cn = c_sm[h * 128 + nloc];
        const float4* tp = (const float4*)(g_t + h * NN + m0 + kq * 16);
        float w[16];
#pragma unroll
        for (int q = 0; q < 4; q++) {
            float4 t4 = __ldg(tp + q);
            float tv[4] = {t4.x, t4.y, t4.z, t4.w};
#pragma unroll
            for (int r = 0; r < 4; r++) {
                float sc = sv * tv[r];
                float mult = sc >= 0.f ? L2E : (ALPHA * L2E);
                float y = fmaxf(fmaf(sc, mult, cn), -126.f);
                w[q * 4 + r] = tf32r(fex2(y));
            }
        }
        float* d = As + nloc * ST + kq * 16;
        *(float4*)d        = make_float4(w[0], w[1], w[2], w[3]);
        *(float4*)(d + 4)  = make_float4(w[4], w[5], w[6], w[7]);
        *(float4*)(d + 8)  = make_float4(w[8], w[9], w[10], w[11]);
        *(float4*)(d + 12) = make_float4(w[12], w[13], w[14], w[15]);
        const float* bsrc = g_featsT + (size_t)h * FF * NN
                          + (size_t)(f0 + prow) * NN + m0 + pseg * 16;
        uint32_t bd = smem_u32(Bs + prow * ST + pseg * 16);
#pragma unroll
        for (int j = 0; j < 4; j++) cpasync16(bd + j * 16, bsrc + j * 4);
    };
    auto domma = [&](int s) {
        float* As = sm + A_CONST + s * A_STG;
        float* Bs = As + 128 * ST;
#pragma unroll
        for (int kk = 0; kk < 2; kk++) {
            int ks = kw * 2 + kk;
            uint32_t a[4][4];
#pragma unroll
            for (int mt = 0; mt < 4; mt++) {
                int base = warp_m * 64 + mt * 16;
                a[mt][0] = __float_as_uint(As[(base + g) * ST + ks * 8 + tg]);
                a[mt][1] = __float_as_uint(As[(base + 8 + g) * ST + ks * 8 + tg]);
                a[mt][2] = __float_as_uint(As[(base + g) * ST + ks * 8 + tg + 4]);
                a[mt][3] = __float_as_uint(As[(base + 8 + g) * ST + ks * 8 + tg + 4]);
            }
#pragma unroll
            for (int nt = 0; nt < 8; nt++) {
                int fc = warp_n * 64 + nt * 8 + g;
                uint32_t b0 = __float_as_uint(Bs[fc * ST + ks * 8 + tg]);
                uint32_t b1 = __float_as_uint(Bs[fc * ST + ks * 8 + tg + 4]);
#pragma unroll
                for (int mt = 0; mt < 4; mt++)
                    mma1688(acc[mt][nt], a[mt], b0, b1);
            }
        }
    };

    const int NIT = HH * (NN / 32);   // 512
    __syncthreads();                  // s_sm/c_sm ready
    prod(0, 0); cp_commit();
    for (int i = 0; i < NIT; i++) {
        cp_wait<0>();
        __syncthreads();
        if (i + 1 < NIT) { prod(i + 1, (i + 1) & 1); cp_commit(); }
        domma(i & 1);
    }

    // merge k-group 1 into k-group 0 via smem (reuse stage area)
    float* red = sm + A_CONST;
    __syncthreads();
    if (kw == 1) {
        float4* dst = (float4*)&red[(wq * 32 + lane) * RED_STRIDE];
        const float4* src = (const float4*)&acc[0][0][0];
#pragma unroll
        for (int j = 0; j < 32; j++) dst[j] = src[j];
    }
    __syncthreads();
    if (kw == 0) {
        const float4* src = (const float4*)&red[(wq * 32 + lane) * RED_STRIDE];
        float* ap = &acc[0][0][0];
#pragma unroll
        for (int j = 0; j < 32; j++) {
            float4 v = src[j];
            ap[j * 4 + 0] += v.x; ap[j * 4 + 1] += v.y;
            ap[j * 4 + 2] += v.z; ap[j * 4 + 3] += v.w;
        }
#pragma unroll
        for (int mt = 0; mt < 4; mt++) {
#pragma unroll
            for (int nt = 0; nt < 8; nt++) {
                int row = n0 + warp_m * 64 + mt * 16 + g;
                int col = f0 + warp_n * 64 + nt * 8 + tg * 2;
                float2 v0, v1;
                v0.x = fmaxf(0.25f * acc[mt][nt][0], 0.f);
                v0.y = fmaxf(0.25f * acc[mt][nt][1], 0.f);
                v1.x = fmaxf(0.25f * acc[mt][nt][2], 0.f);
                v1.y = fmaxf(0.25f * acc[mt][nt][3], 0.f);
                *(float2*)(out + (size_t)row * FF + col) = v0;
                *(float2*)(out + (size_t)(row + 8) * FF + col) = v1;
            }
        }
    }
}

// ================= launch =================
extern "C" void kernel_launch(void* const* d_in, const int* in_sizes, int n_in,
                              void* d_out, int out_size)
{
    const float* nodes  = (const float*)d_in[0];
    const float* edges  = (const float*)d_in[1];
    const float* labels = (const float*)d_in[2];
    const float* We     = (const float*)d_in[3];
    const float* be     = (const float*)d_in[4];
    const float* Wm     = (const float*)d_in[5];
    const float* b      = (const float*)d_in[6];
    const float* u      = (const float*)d_in[7];
    const float* v      = (const float*)d_in[8];
    float* out = (float*)d_out;

    static bool attr_done = false;
    if (!attr_done) {
        cudaFuncSetAttribute(feats_gemm, cudaFuncAttributeMaxDynamicSharedMemorySize, F_SMEM);
        cudaFuncSetAttribute(attn_gemm, cudaFuncAttributeMaxDynamicSharedMemorySize, A_SMEM);
        cudaFuncSetAttribute(feats_gemm, cudaFuncAttributePreferredSharedMemoryCarveout, 100);
        cudaFuncSetAttribute(attn_gemm, cudaFuncAttributePreferredSharedMemoryCarveout, 100);
        attr_done = true;
    }

    setup_kernel<<<SETUP_BLOCKS, 256>>>(nodes, edges, labels, Wm, We, b, be, u, v);
    st_kernel<<<HH * NN / 8, 256>>>(nodes);
    minmax_kernel<<<HH, 256>>>();
    feats_gemm<<<dim3(FF / 128, NN / 128, HH), 256, F_SMEM>>>();  // capture slot 4
    z_kernel<<<HH * NN / 8, 256>>>();
    attn_gemm<<<dim3(FF / 128, NN / 128), 256, A_SMEM>>>(out);
}

// round 15
// speedup vs baseline: 1.1747x; 1.1747x over previous
#include <cuda_runtime.h>
#include <cstdint>

#define NN 4096
#define DD 512
#define FF 512
#define HH 4
#define KK 1024
#define ALPHA 0.3f
#define L2E 1.4426950408889634f
#define ST 36        // feats smem row stride (BK=32 + pad)
#define ST2 68       // attn smem row stride (BK=64 + pad)

// ---- scratch (device globals; no allocation allowed) ----
__device__ float g_A[NN * KK];          // tf32-rounded [nodes | edges+labels], [m][k]
__device__ float g_BT[HH * FF * KK];    // tf32-rounded [h][f][k] = [W^T | We^T]
__device__ float g_bias2[HH * FF];
__device__ float g_featsT[(size_t)HH * FF * NN];  // [h][f][m], tf32-rounded
__device__ float g_s[HH * NN];
__device__ float g_t[HH * NN];
__device__ float g_rmax[HH * NN];
__device__ float g_invz[HH * NN];
__device__ float g_wu[HH * DD];
__device__ float g_wv[HH * DD];
__device__ float g_bu[HH];
__device__ float g_bv[HH];
__device__ float g_hpmax[HH];
__device__ float g_hmmin[HH];

// ================= helpers =================
__device__ __forceinline__ float warp_sum(float x) {
#pragma unroll
    for (int o = 16; o > 0; o >>= 1) x += __shfl_xor_sync(0xffffffffu, x, o);
    return x;
}
__device__ __forceinline__ uint32_t cvt_tf32(float x) {
    uint32_t r; asm("cvt.rna.tf32.f32 %0, %1;" : "=r"(r) : "f"(x)); return r;
}
__device__ __forceinline__ float tf32r(float x) {
    return __uint_as_float(cvt_tf32(x));
}
__device__ __forceinline__ float fex2(float y) {
    float r; asm("ex2.approx.ftz.f32 %0, %1;" : "=f"(r) : "f"(y)); return r;
}
__device__ __forceinline__ uint32_t smem_u32(const void* p) {
    uint32_t a;
    asm("{ .reg .u64 t; cvta.to.shared.u64 t, %1; cvt.u32.u64 %0, t; }"
        : "=r"(a) : "l"(p));
    return a;
}
__device__ __forceinline__ void cpasync16(uint32_t dst, const void* src) {
    asm volatile("cp.async.cg.shared.global [%0], [%1], 16;" :: "r"(dst), "l"(src));
}
__device__ __forceinline__ void cp_commit() {
    asm volatile("cp.async.commit_group;" ::: "memory");
}
template <int N>
__device__ __forceinline__ void cp_wait() {
    asm volatile("cp.async.wait_group %0;" :: "n"(N) : "memory");
}
__device__ __forceinline__ void mma1688(float* c, const uint32_t* a, uint32_t b0, uint32_t b1) {
    asm volatile(
        "mma.sync.aligned.m16n8k8.row.col.f32.tf32.tf32.f32 "
        "{%0,%1,%2,%3}, {%4,%5,%6,%7}, {%8,%9}, {%0,%1,%2,%3};"
        : "+f"(c[0]), "+f"(c[1]), "+f"(c[2]), "+f"(c[3])
        : "r"(a[0]), "r"(a[1]), "r"(a[2]), "r"(a[3]), "r"(b0), "r"(b1));
}

// ================= fused setup kernel =================
#define SETUP_BLOCKS 4361

__global__ __launch_bounds__(256) void setup_kernel(
    const float* __restrict__ nodes, const float* __restrict__ edges,
    const float* __restrict__ labels, const float* __restrict__ W,
    const float* __restrict__ We, const float* __restrict__ b,
    const float* __restrict__ be, const float* __restrict__ u,
    const float* __restrict__ v)
{
    __shared__ float tile[32][33];
    int bx = blockIdx.x;
    int tid = threadIdx.x;
    if (bx < 2048) {
        int i = bx * 256 + tid;           // float4 index over NN*DD/4
        int m = i >> 7, dq = i & 127;
        float4 a = ((const float4*)nodes)[i];
        float4 x = ((const float4*)edges)[i];
        float4 y = ((const float4*)labels)[i];
        float* h0 = g_A + (size_t)m * KK + dq * 4;
        float av[4] = {a.x, a.y, a.z, a.w};
        float cv[4] = {x.x + y.x, x.y + y.y, x.z + y.z, x.w + y.w};
#pragma unroll
        for (int j = 0; j < 4; j++) {
            h0[j] = tf32r(av[j]);
            h0[DD + j] = tf32r(cv[j]);
        }
    } else if (bx < 4096) {
        int jb = bx - 2048;
        int h = jb >> 9;
        int r = jb & 511;
        int k0 = (r >> 4) * 32, f0 = (r & 15) * 32;
        int tx = tid & 31, ty0 = tid >> 5;
#pragma unroll
        for (int j = 0; j < 4; j++) {
            int ty = ty0 * 4 + j;
            int k = k0 + ty;
            float vv = (k < DD) ? W[((size_t)h * DD + k) * FF + f0 + tx]
                                : We[(size_t)(k - DD) * FF + f0 + tx];
            tile[ty][tx] = vv;
        }
        __syncthreads();
#pragma unroll
        for (int j = 0; j < 4; j++) {
            int ty = ty0 * 4 + j;
            g_BT[((size_t)h * FF + f0 + ty) * KK + k0 + tx] = tf32r(tile[tx][ty]);
        }
    } else if (bx < 4104) {
        int i = (bx - 4096) * 256 + tid;
        int f = i & (FF - 1);
        g_bias2[i] = b[i] + be[f];
    } else if (bx < 4360) {
        int w = (bx - 4104) * 8 + (tid >> 5);
        int lane = tid & 31;
        int h = w / DD, d = w % DD;
        const float4* Wr = (const float4*)(W + ((long)h * DD + d) * FF);
        const float4* up = (const float4*)(u + (long)h * FF);
        const float4* vp = (const float4*)(v + (long)h * FF);
        float su = 0.f, sv = 0.f;
        for (int i = lane; i < FF / 4; i += 32) {
            float4 w4 = Wr[i], u4 = up[i], v4 = vp[i];
            su += w4.x * u4.x + w4.y * u4.y + w4.z * u4.z + w4.w * u4.w;
            sv += w4.x * v4.x + w4.y * v4.y + w4.z * v4.z + w4.w * v4.w;
        }
        su = warp_sum(su); sv = warp_sum(sv);
        if (lane == 0) { g_wu[h * DD + d] = su; g_wv[h * DD + d] = sv; }
    } else {
        if (tid < 128) {
            int h = tid >> 5;
            int lane = tid & 31;
            float su = 0.f, sv = 0.f;
            for (int i = lane; i < FF; i += 32) {
                float bb = b[h * FF + i];
                su += bb * u[h * FF + i];
                sv += bb * v[h * FF + i];
            }
            su = warp_sum(su); sv = warp_sum(sv);
            if (lane == 0) { g_bu[h] = su; g_bv[h] = sv; }
        }
    }
}

// ================= rank-1 precomputation =================
__global__ __launch_bounds__(256) void st_kernel(const float* __restrict__ nodes) {
    int w = blockIdx.x * 8 + (threadIdx.x >> 5);
    int lane = threadIdx.x & 31;
    int h = w >> 12;
    int n = w & (NN - 1);
    const float4* nr = (const float4*)(nodes + (long)n * DD);
    const float4* wu = (const float4*)(g_wu + (long)h * DD);
    const float4* wv = (const float4*)(g_wv + (long)h * DD);
    float ss = 0.f, tt = 0.f;
    for (int i = lane; i < DD / 4; i += 32) {
        float4 x = nr[i], a = wu[i], c = wv[i];
        ss += x.x * a.x + x.y * a.y + x.z * a.z + x.w * a.w;
        tt += x.x * c.x + x.y * c.y + x.z * c.z + x.w * c.w;
    }
    ss = warp_sum(ss); tt = warp_sum(tt);
    if (lane == 0) {
        g_s[h * NN + n] = ss + g_bu[h];
        g_t[h * NN + n] = tt + g_bv[h];
    }
}

__global__ void minmax_kernel() {
    int h = blockIdx.x;
    int tid = threadIdx.x;
    __shared__ float smx[256], smn[256];
    float mx = -1e30f, mn = 1e30f;
    for (int m = tid; m < NN; m += 256) {
        float t = g_t[h * NN + m];
        float hp = t >= 0.f ? t : ALPHA * t;
        float hm = t <= 0.f ? t : ALPHA * t;
        mx = fmaxf(mx, hp);
        mn = fminf(mn, hm);
    }
    smx[tid] = mx; smn[tid] = mn;
    __syncthreads();
    for (int sft = 128; sft > 0; sft >>= 1) {
        if (tid < sft) {
            smx[tid] = fmaxf(smx[tid], smx[tid + sft]);
            smn[tid] = fminf(smn[tid], smn[tid + sft]);
        }
        __syncthreads();
    }
    if (tid == 0) { g_hpmax[h] = smx[0]; g_hmmin[h] = smn[0]; }
}

__global__ __launch_bounds__(256) void z_kernel() {
    int w = blockIdx.x * 8 + (threadIdx.x >> 5);
    int lane = threadIdx.x & 31;
    int h = w >> 12, n = w & (NN - 1);
    float s = g_s[h * NN + n];
    float rmax = s > 0.f ? s * g_hpmax[h] : (s < 0.f ? s * g_hmmin[h] : 0.f);
    const float* tp = g_t + (long)h * NN;
    float z = 0.f;
    for (int m = lane; m < NN; m += 32) {
        float sc = s * tp[m];
        sc = sc >= 0.f ? sc : ALPHA * sc;
        z += fex2(fmaxf((sc - rmax) * L2E, -126.f));
    }
    z = warp_sum(z);
    if (lane == 0) {
        g_rmax[h * NN + n] = rmax;
        g_invz[h * NN + n] = 1.f / z;
    }
}

// ======== feats GEMM: R9 config (3-stage, BK=32, 32x64 warps, 1 barrier) ========
#define F_AS (128 * ST)            // 4608 floats
#define F_STG (2 * F_AS)           // 9216 floats (A + B)
#define F_SMEM (3 * F_STG * 4)     // 110592 bytes -> 2 CTAs/SM

__global__ __launch_bounds__(256) void feats_gemm() {
    extern __shared__ float sm[];
    int tid = threadIdx.x, wid = tid >> 5, lane = tid & 31;
    int g = lane >> 2, tg = lane & 3;
    int h = blockIdx.z;
    int m0 = blockIdx.y * 128, f0 = blockIdx.x * 128;
    const float* Bp = g_BT + (size_t)h * FF * KK;
    int warp_m = wid & 3, warp_n = wid >> 2;

    float acc[2][8][4];
#pragma unroll
    for (int a = 0; a < 2; a++)
#pragma unroll
        for (int bq = 0; bq < 8; bq++)
#pragma unroll
            for (int c = 0; c < 4; c++) acc[a][bq][c] = 0.f;

    int prow = tid & 127, pseg = tid >> 7;

    auto prod = [&](int c, int s) {
        float* As = sm + s * F_STG;
        float* Bs = As + F_AS;
        int k0 = c * 32;
        const float* asrc = g_A + (size_t)(m0 + prow) * KK + k0 + pseg * 16;
        const float* bsrc = Bp + (size_t)(f0 + prow) * KK + k0 + pseg * 16;
        uint32_t ad = smem_u32(As + prow * ST + pseg * 16);
        uint32_t bd = smem_u32(Bs + prow * ST + pseg * 16);
#pragma unroll
        for (int j = 0; j < 4; j++) {
            cpasync16(ad + j * 16, asrc + j * 4);
            cpasync16(bd + j * 16, bsrc + j * 4);
        }
    };
    auto domma = [&](int s) {
        float* As = sm + s * F_STG;
        float* Bs = As + F_AS;
#pragma unroll
        for (int ks = 0; ks < 4; ks++) {
            uint32_t a[2][4];
#pragma unroll
            for (int mt = 0; mt < 2; mt++) {
                int base = warp_m * 32 + mt * 16;
                a[mt][0] = __float_as_uint(As[(base + g) * ST + ks * 8 + tg]);
                a[mt][1] = __float_as_uint(As[(base + 8 + g) * ST + ks * 8 + tg]);
                a[mt][2] = __float_as_uint(As[(base + g) * ST + ks * 8 + tg + 4]);
                a[mt][3] = __float_as_uint(As[(base + 8 + g) * ST + ks * 8 + tg + 4]);
            }
#pragma unroll
            for (int nt = 0; nt < 8; nt++) {
                int fc = warp_n * 64 + nt * 8 + g;
                uint32_t b0 = __float_as_uint(Bs[fc * ST + ks * 8 + tg]);
                uint32_t b1 = __float_as_uint(Bs[fc * ST + ks * 8 + tg + 4]);
                mma1688(acc[0][nt], a[0], b0, b1);
                mma1688(acc[1][nt], a[1], b0, b1);
            }
        }
    };

    const int NIT = KK / 32;   // 32
    prod(0, 0); cp_commit();
    prod(1, 1); cp_commit();
    cp_wait<1>();
    __syncthreads();
    for (int i = 0; i < NIT; i++) {
        domma(i % 3);
        if (i + 2 < NIT) { prod(i + 2, (i + 2) % 3); cp_commit(); cp_wait<1>(); }
        else if (i + 2 == NIT) cp_wait<0>();
        __syncthreads();
    }

    float* dst = g_featsT + (size_t)h * FF * NN;
#pragma unroll
    for (int mt = 0; mt < 2; mt++) {
#pragma unroll
        for (int nt = 0; nt < 8; nt++) {
            int row = m0 + warp_m * 32 + mt * 16 + g;
            int col = f0 + warp_n * 64 + nt * 8 + tg * 2;
            float b0v = g_bias2[h * FF + col];
            float b1v = g_bias2[h * FF + col + 1];
            dst[(size_t)col * NN + row]           = tf32r(acc[mt][nt][0] + b0v);
            dst[(size_t)(col + 1) * NN + row]     = tf32r(acc[mt][nt][1] + b1v);
            dst[(size_t)col * NN + row + 8]       = tf32r(acc[mt][nt][2] + b0v);
            dst[(size_t)(col + 1) * NN + row + 8] = tf32r(acc[mt][nt][3] + b1v);
        }
    }
}

// ======== fused attention GEMM: BK=64, 3-stage, 512 thr, 4x4 warps 32x32 ========
// CTA 128n x 128f, grid (4, 32) = 128 CTAs. 256 iterations over (h, 64-m chunks).
// w = 2^( s_n*t_m * (>=0 ? L2E : 0.3*L2E) + C_n ), C_n = log2(invz_n) - rmax_n*L2E
#define A_CONST 1024                // s_sm[512] + c_sm[512]
#define A_AS (128 * ST2)            // 8704 floats
#define A_STG (2 * A_AS)            // A + B = 17408 floats
#define A_SMEM ((A_CONST + 3 * A_STG) * 4)   // 212992 bytes

__global__ __launch_bounds__(512) void attn_gemm(float* __restrict__ out) {
    extern __shared__ float sm[];
    float* s_sm = sm;              // [4h][128]
    float* c_sm = sm + 512;        // [4h][128]
    int tid = threadIdx.x, wid = tid >> 5, lane = tid & 31;
    int g = lane >> 2, tg = lane & 3;
    int n0 = blockIdx.y * 128, f0 = blockIdx.x * 128;
    int warp_m = wid & 3, warp_n = wid >> 2;

    {
        int hh = tid >> 7, nl = tid & 127;    // 512 = 4*128
        float iz = g_invz[hh * NN + n0 + nl];
        float rm = g_rmax[hh * NN + n0 + nl];
        s_sm[tid] = g_s[hh * NN + n0 + nl];
        c_sm[tid] = __log2f(iz) - rm * L2E;
    }

    float acc[2][4][4];
#pragma unroll
    for (int a = 0; a < 2; a++)
#pragma unroll
        for (int bq = 0; bq < 4; bq++)
#pragma unroll
            for (int c = 0; c < 4; c++) acc[a][bq][c] = 0.f;

    int nloc = tid & 127, kq = tid >> 7;      // weight gen: 16 k's each (kq 0..3)
    int prow = tid >> 2, pseg = tid & 3;      // B copy: 4 x 16B per thread

    auto prod = [&](int c, int s) {
        float* As = sm + A_CONST + s * A_STG;
        float* Bs = As + A_AS;
        int h = c >> 6;
        int m0 = (c & 63) << 6;               // 64 m per iteration
        float sv = s_sm[h * 128 + nloc];
        float cn = c_sm[h * 128 + nloc];
        const float4* tp = (const float4*)(g_t + h * NN + m0 + kq * 16);
        float w[16];
#pragma unroll
        for (int q = 0; q < 4; q++) {
            float4 t4 = __ldg(tp + q);
            float tv[4] = {t4.x, t4.y, t4.z, t4.w};
#pragma unroll
            for (int r = 0; r < 4; r++) {
                float sc = sv * tv[r];
                float mult = sc >= 0.f ? L2E : (ALPHA * L2E);
                float y = fmaxf(fmaf(sc, mult, cn), -126.f);
                w[q * 4 + r] = tf32r(fex2(y));
            }
        }
        float* d = As + nloc * ST2 + kq * 16;
        *(float4*)d        = make_float4(w[0], w[1], w[2], w[3]);
        *(float4*)(d + 4)  = make_float4(w[4], w[5], w[6], w[7]);
        *(float4*)(d + 8)  = make_float4(w[8], w[9], w[10], w[11]);
        *(float4*)(d + 12) = make_float4(w[12], w[13], w[14], w[15]);
        // B tile: featsT[h][f0+prow][m0 .. +64), 64 floats per row
        const float* bsrc = g_featsT + (size_t)h * FF * NN
                          + (size_t)(f0 + prow) * NN + m0 + pseg * 16;
        uint32_t bd = smem_u32(Bs + prow * ST2 + pseg * 16);
#pragma unroll
        for (int j = 0; j < 4; j++) cpasync16(bd + j * 16, bsrc + j * 4);
    };
    auto domma = [&](int s) {
        float* As = sm + A_CONST + s * A_STG;
        float* Bs = As + A_AS;
#pragma unroll
        for (int ks = 0; ks < 8; ks++) {
            uint32_t a[2][4];
#pragma unroll
            for (int mt = 0; mt < 2; mt++) {
                int base = warp_m * 32 + mt * 16;
                a[mt][0] = __float_as_uint(As[(base + g) * ST2 + ks * 8 + tg]);
                a[mt][1] = __float_as_uint(As[(base + 8 + g) * ST2 + ks * 8 + tg]);
                a[mt][2] = __float_as_uint(As[(base + g) * ST2 + ks * 8 + tg + 4]);
                a[mt][3] = __float_as_uint(As[(base + 8 + g) * ST2 + ks * 8 + tg + 4]);
            }
#pragma unroll
            for (int nt = 0; nt < 4; nt++) {
                int fc = warp_n * 32 + nt * 8 + g;
                uint32_t b0 = __float_as_uint(Bs[fc * ST2 + ks * 8 + tg]);
                uint32_t b1 = __float_as_uint(Bs[fc * ST2 + ks * 8 + tg + 4]);
                mma1688(acc[0][nt], a[0], b0, b1);
                mma1688(acc[1][nt], a[1], b0, b1);
            }
        }
    };

    const int NIT = HH * (NN / 64);   // 256
    __syncthreads();                  // s_sm/c_sm ready (prod reads them)
    prod(0, 0); cp_commit();
    prod(1, 1); cp_commit();
    cp_wait<1>();
    __syncthreads();
    for (int i = 0; i < NIT; i++) {
        domma(i % 3);
        if (i + 2 < NIT) { prod(i + 2, (i + 2) % 3); cp_commit(); cp_wait<1>(); }
        else if (i + 2 == NIT) cp_wait<0>();
        __syncthreads();
    }

#pragma unroll
    for (int mt = 0; mt < 2; mt++) {
#pragma unroll
        for (int nt = 0; nt < 4; nt++) {
            int row = n0 + warp_m * 32 + mt * 16 + g;
            int col = f0 + warp_n * 32 + nt * 8 + tg * 2;
            float2 v0, v1;
            v0.x = fmaxf(0.25f * acc[mt][nt][0], 0.f);
            v0.y = fmaxf(0.25f * acc[mt][nt][1], 0.f);
            v1.x = fmaxf(0.25f * acc[mt][nt][2], 0.f);
            v1.y = fmaxf(0.25f * acc[mt][nt][3], 0.f);
            *(float2*)(out + (size_t)row * FF + col) = v0;
            *(float2*)(out + (size_t)(row + 8) * FF + col) = v1;
        }
    }
}

// ================= launch =================
extern "C" void kernel_launch(void* const* d_in, const int* in_sizes, int n_in,
                              void* d_out, int out_size)
{
    const float* nodes  = (const float*)d_in[0];
    const float* edges  = (const float*)d_in[1];
    const float* labels = (const float*)d_in[2];
    const float* We     = (const float*)d_in[3];
    const float* be     = (const float*)d_in[4];
    const float* Wm     = (const float*)d_in[5];
    const float* b      = (const float*)d_in[6];
    const float* u      = (const float*)d_in[7];
    const float* v      = (const float*)d_in[8];
    float* out = (float*)d_out;

    static bool attr_done = false;
    if (!attr_done) {
        cudaFuncSetAttribute(feats_gemm, cudaFuncAttributeMaxDynamicSharedMemorySize, F_SMEM);
        cudaFuncSetAttribute(attn_gemm, cudaFuncAttributeMaxDynamicSharedMemorySize, A_SMEM);
        cudaFuncSetAttribute(feats_gemm, cudaFuncAttributePreferredSharedMemoryCarveout, 100);
        cudaFuncSetAttribute(attn_gemm, cudaFuncAttributePreferredSharedMemoryCarveout, 100);
        attr_done = true;
    }

    setup_kernel<<<SETUP_BLOCKS, 256>>>(nodes, edges, labels, Wm, We, b, be, u, v);
    st_kernel<<<HH * NN / 8, 256>>>(nodes);
    minmax_kernel<<<HH, 256>>>();
    feats_gemm<<<dim3(FF / 128, NN / 128, HH), 256, F_SMEM>>>();  // capture slot 4
    z_kernel<<<HH * NN / 8, 256>>>();
    attn_gemm<<<dim3(FF / 128, NN / 128), 512, A_SMEM>>>(out);
}

// round 16
// speedup vs baseline: 1.2874x; 1.0960x over previous
#include <cuda_runtime.h>
#include <cstdint>

#define NN 4096
#define DD 512
#define FF 512
#define HH 4
#define KK 1024
#define ALPHA 0.3f
#define L2E 1.4426950408889634f
#define ST 36        // feats smem row stride (BK=32 + pad), 144B = 9*16
#define ST2 68       // attn smem row stride (BK=64 + pad), 272B = 17*16

// ---- scratch (device globals; no allocation allowed) ----
__device__ float g_A[NN * KK];          // tf32-rounded [nodes | edges+labels], [m][k]
__device__ float g_BT[HH * FF * KK];    // tf32-rounded [h][f][k] = [W^T | We^T]
__device__ float g_bias2[HH * FF];
__device__ float g_featsT[(size_t)HH * FF * NN];  // [h][f][m], tf32-rounded
__device__ float g_s[HH * NN];
__device__ float g_t[HH * NN];
__device__ float g_rmax[HH * NN];
__device__ float g_invz[HH * NN];
__device__ float g_wu[HH * DD];
__device__ float g_wv[HH * DD];
__device__ float g_bu[HH];
__device__ float g_bv[HH];
__device__ float g_hpmax[HH];
__device__ float g_hmmin[HH];

// ================= helpers =================
__device__ __forceinline__ float warp_sum(float x) {
#pragma unroll
    for (int o = 16; o > 0; o >>= 1) x += __shfl_xor_sync(0xffffffffu, x, o);
    return x;
}
__device__ __forceinline__ uint32_t cvt_tf32(float x) {
    uint32_t r; asm("cvt.rna.tf32.f32 %0, %1;" : "=r"(r) : "f"(x)); return r;
}
__device__ __forceinline__ float tf32r(float x) {
    return __uint_as_float(cvt_tf32(x));
}
__device__ __forceinline__ float fex2(float y) {
    float r; asm("ex2.approx.ftz.f32 %0, %1;" : "=f"(r) : "f"(y)); return r;
}
__device__ __forceinline__ uint32_t smem_u32(const void* p) {
    uint32_t a;
    asm("{ .reg .u64 t; cvta.to.shared.u64 t, %1; cvt.u32.u64 %0, t; }"
        : "=r"(a) : "l"(p));
    return a;
}
__device__ __forceinline__ void cpasync16(uint32_t dst, const void* src) {
    asm volatile("cp.async.cg.shared.global [%0], [%1], 16;" :: "r"(dst), "l"(src));
}
__device__ __forceinline__ void cp_commit() {
    asm volatile("cp.async.commit_group;" ::: "memory");
}
template <int N>
__device__ __forceinline__ void cp_wait() {
    asm volatile("cp.async.wait_group %0;" :: "n"(N) : "memory");
}
__device__ __forceinline__ void ldsm4(uint32_t* r, uint32_t addr) {
    asm volatile("ldmatrix.sync.aligned.m8n8.x4.shared.b16 {%0,%1,%2,%3}, [%4];"
        : "=r"(r[0]), "=r"(r[1]), "=r"(r[2]), "=r"(r[3]) : "r"(addr));
}
__device__ __forceinline__ void mma1688(float* c, const uint32_t* a, uint32_t b0, uint32_t b1) {
    asm volatile(
        "mma.sync.aligned.m16n8k8.row.col.f32.tf32.tf32.f32 "
        "{%0,%1,%2,%3}, {%4,%5,%6,%7}, {%8,%9}, {%0,%1,%2,%3};"
        : "+f"(c[0]), "+f"(c[1]), "+f"(c[2]), "+f"(c[3])
        : "r"(a[0]), "r"(a[1]), "r"(a[2]), "r"(a[3]), "r"(b0), "r"(b1));
}

// ================= fused setup kernel =================
#define SETUP_BLOCKS 4361

__global__ __launch_bounds__(256) void setup_kernel(
    const float* __restrict__ nodes, const float* __restrict__ edges,
    const float* __restrict__ labels, const float* __restrict__ W,
    const float* __restrict__ We, const float* __restrict__ b,
    const float* __restrict__ be, const float* __restrict__ u,
    const float* __restrict__ v)
{
    __shared__ float tile[32][33];
    int bx = blockIdx.x;
    int tid = threadIdx.x;
    if (bx < 2048) {
        int i = bx * 256 + tid;           // float4 index over NN*DD/4
        int m = i >> 7, dq = i & 127;
        float4 a = ((const float4*)nodes)[i];
        float4 x = ((const float4*)edges)[i];
        float4 y = ((const float4*)labels)[i];
        float* h0 = g_A + (size_t)m * KK + dq * 4;
        float av[4] = {a.x, a.y, a.z, a.w};
        float cv[4] = {x.x + y.x, x.y + y.y, x.z + y.z, x.w + y.w};
#pragma unroll
        for (int j = 0; j < 4; j++) {
            h0[j] = tf32r(av[j]);
            h0[DD + j] = tf32r(cv[j]);
        }
    } else if (bx < 4096) {
        int jb = bx - 2048;
        int h = jb >> 9;
        int r = jb & 511;
        int k0 = (r >> 4) * 32, f0 = (r & 15) * 32;
        int tx = tid & 31, ty0 = tid >> 5;
#pragma unroll
        for (int j = 0; j < 4; j++) {
            int ty = ty0 * 4 + j;
            int k = k0 + ty;
            float vv = (k < DD) ? W[((size_t)h * DD + k) * FF + f0 + tx]
                                : We[(size_t)(k - DD) * FF + f0 + tx];
            tile[ty][tx] = vv;
        }
        __syncthreads();
#pragma unroll
        for (int j = 0; j < 4; j++) {
            int ty = ty0 * 4 + j;
            g_BT[((size_t)h * FF + f0 + ty) * KK + k0 + tx] = tf32r(tile[tx][ty]);
        }
    } else if (bx < 4104) {
        int i = (bx - 4096) * 256 + tid;
        int f = i & (FF - 1);
        g_bias2[i] = b[i] + be[f];
    } else if (bx < 4360) {
        int w = (bx - 4104) * 8 + (tid >> 5);
        int lane = tid & 31;
        int h = w / DD, d = w % DD;
        const float4* Wr = (const float4*)(W + ((long)h * DD + d) * FF);
        const float4* up = (const float4*)(u + (long)h * FF);
        const float4* vp = (const float4*)(v + (long)h * FF);
        float su = 0.f, sv = 0.f;
        for (int i = lane; i < FF / 4; i += 32) {
            float4 w4 = Wr[i], u4 = up[i], v4 = vp[i];
            su += w4.x * u4.x + w4.y * u4.y + w4.z * u4.z + w4.w * u4.w;
            sv += w4.x * v4.x + w4.y * v4.y + w4.z * v4.z + w4.w * v4.w;
        }
        su = warp_sum(su); sv = warp_sum(sv);
        if (lane == 0) { g_wu[h * DD + d] = su; g_wv[h * DD + d] = sv; }
    } else {
        if (tid < 128) {
            int h = tid >> 5;
            int lane = tid & 31;
            float su = 0.f, sv = 0.f;
            for (int i = lane; i < FF; i += 32) {
                float bb = b[h * FF + i];
                su += bb * u[h * FF + i];
                sv += bb * v[h * FF + i];
            }
            su = warp_sum(su); sv = warp_sum(sv);
            if (lane == 0) { g_bu[h] = su; g_bv[h] = sv; }
        }
    }
}

// ================= rank-1 precomputation =================
__global__ __launch_bounds__(256) void st_kernel(const float* __restrict__ nodes) {
    int w = blockIdx.x * 8 + (threadIdx.x >> 5);
    int lane = threadIdx.x & 31;
    int h = w >> 12;
    int n = w & (NN - 1);
    const float4* nr = (const float4*)(nodes + (long)n * DD);
    const float4* wu = (const float4*)(g_wu + (long)h * DD);
    const float4* wv = (const float4*)(g_wv + (long)h * DD);
    float ss = 0.f, tt = 0.f;
    for (int i = lane; i < DD / 4; i += 32) {
        float4 x = nr[i], a = wu[i], c = wv[i];
        ss += x.x * a.x + x.y * a.y + x.z * a.z + x.w * a.w;
        tt += x.x * c.x + x.y * c.y + x.z * c.z + x.w * c.w;
    }
    ss = warp_sum(ss); tt = warp_sum(tt);
    if (lane == 0) {
        g_s[h * NN + n] = ss + g_bu[h];
        g_t[h * NN + n] = tt + g_bv[h];
    }
}

__global__ void minmax_kernel() {
    int h = blockIdx.x;
    int tid = threadIdx.x;
    __shared__ float smx[256], smn[256];
    float mx = -1e30f, mn = 1e30f;
    for (int m = tid; m < NN; m += 256) {
        float t = g_t[h * NN + m];
        float hp = t >= 0.f ? t : ALPHA * t;
        float hm = t <= 0.f ? t : ALPHA * t;
        mx = fmaxf(mx, hp);
        mn = fminf(mn, hm);
    }
    smx[tid] = mx; smn[tid] = mn;
    __syncthreads();
    for (int sft = 128; sft > 0; sft >>= 1) {
        if (tid < sft) {
            smx[tid] = fmaxf(smx[tid], smx[tid + sft]);
            smn[tid] = fminf(smn[tid], smn[tid + sft]);
        }
        __syncthreads();
    }
    if (tid == 0) { g_hpmax[h] = smx[0]; g_hmmin[h] = smn[0]; }
}

__global__ __launch_bounds__(256) void z_kernel() {
    int w = blockIdx.x * 8 + (threadIdx.x >> 5);
    int lane = threadIdx.x & 31;
    int h = w >> 12, n = w & (NN - 1);
    float s = g_s[h * NN + n];
    float rmax = s > 0.f ? s * g_hpmax[h] : (s < 0.f ? s * g_hmmin[h] : 0.f);
    const float* tp = g_t + (long)h * NN;
    float z = 0.f;
    for (int m = lane; m < NN; m += 32) {
        float sc = s * tp[m];
        sc = sc >= 0.f ? sc : ALPHA * sc;
        z += fex2(fmaxf((sc - rmax) * L2E, -126.f));
    }
    z = warp_sum(z);
    if (lane == 0) {
        g_rmax[h * NN + n] = rmax;
        g_invz[h * NN + n] = 1.f / z;
    }
}

// ======== feats GEMM: 3-stage BK=32, 32x64 warp tiles, ldmatrix frags ========
#define F_AS (128 * ST)            // 4608 floats
#define F_STG (2 * F_AS)           // 9216 floats (A + B)
#define F_SMEM (3 * F_STG * 4)     // 110592 bytes -> 2 CTAs/SM

__global__ __launch_bounds__(256) void feats_gemm() {
    extern __shared__ float sm[];
    uint32_t smb = smem_u32(sm);
    int tid = threadIdx.x, wid = tid >> 5, lane = tid & 31;
    int g = lane >> 2, tg = lane & 3;
    int h = blockIdx.z;
    int m0 = blockIdx.y * 128, f0 = blockIdx.x * 128;
    const float* Bp = g_BT + (size_t)h * FF * KK;
    int warp_m = wid & 3, warp_n = wid >> 2;

    // ldmatrix per-lane address offsets (bytes, within As / Bs areas)
    int l7 = lane & 7, lt = lane >> 3;
    uint32_t aoff[2], boff[4];
#pragma unroll
    for (int mt = 0; mt < 2; mt++)
        aoff[mt] = ((warp_m * 32 + mt * 16 + (lt & 1) * 8 + l7) * ST + (lt >> 1) * 4) * 4;
#pragma unroll
    for (int nt2 = 0; nt2 < 4; nt2++)
        boff[nt2] = ((warp_n * 64 + nt2 * 16 + (lt >> 1) * 8 + l7) * ST + (lt & 1) * 4) * 4;

    float acc[2][8][4];
#pragma unroll
    for (int a = 0; a < 2; a++)
#pragma unroll
        for (int bq = 0; bq < 8; bq++)
#pragma unroll
            for (int c = 0; c < 4; c++) acc[a][bq][c] = 0.f;

    int prow = tid & 127, pseg = tid >> 7;

    auto prod = [&](int c, int s) {
        uint32_t As = smb + s * F_STG * 4;
        uint32_t Bs = As + F_AS * 4;
        int k0 = c * 32;
        const float* asrc = g_A + (size_t)(m0 + prow) * KK + k0 + pseg * 16;
        const float* bsrc = Bp + (size_t)(f0 + prow) * KK + k0 + pseg * 16;
        uint32_t ad = As + (prow * ST + pseg * 16) * 4;
        uint32_t bd = Bs + (prow * ST + pseg * 16) * 4;
#pragma unroll
        for (int j = 0; j < 4; j++) {
            cpasync16(ad + j * 16, asrc + j * 4);
            cpasync16(bd + j * 16, bsrc + j * 4);
        }
    };
    auto domma = [&](int s) {
        uint32_t As = smb + s * F_STG * 4;
        uint32_t Bs = As + F_AS * 4;
#pragma unroll
        for (int ks = 0; ks < 4; ks++) {
            uint32_t a0[4], a1[4];
            ldsm4(a0, As + aoff[0] + ks * 32);
            ldsm4(a1, As + aoff[1] + ks * 32);
#pragma unroll
            for (int nt2 = 0; nt2 < 4; nt2++) {
                uint32_t bfr[4];
                ldsm4(bfr, Bs + boff[nt2] + ks * 32);
                mma1688(acc[0][2 * nt2],     a0, bfr[0], bfr[1]);
                mma1688(acc[1][2 * nt2],     a1, bfr[0], bfr[1]);
                mma1688(acc[0][2 * nt2 + 1], a0, bfr[2], bfr[3]);
                mma1688(acc[1][2 * nt2 + 1], a1, bfr[2], bfr[3]);
            }
        }
    };

    const int NIT = KK / 32;   // 32
    prod(0, 0); cp_commit();
    prod(1, 1); cp_commit();
    cp_wait<1>();
    __syncthreads();
    for (int i = 0; i < NIT; i++) {
        domma(i % 3);
        if (i + 2 < NIT) { prod(i + 2, (i + 2) % 3); cp_commit(); cp_wait<1>(); }
        else if (i + 2 == NIT) cp_wait<0>();
        __syncthreads();
    }

    float* dst = g_featsT + (size_t)h * FF * NN;
#pragma unroll
    for (int mt = 0; mt < 2; mt++) {
#pragma unroll
        for (int nt = 0; nt < 8; nt++) {
            int row = m0 + warp_m * 32 + mt * 16 + g;
            int col = f0 + warp_n * 64 + nt * 8 + tg * 2;
            float b0v = g_bias2[h * FF + col];
            float b1v = g_bias2[h * FF + col + 1];
            dst[(size_t)col * NN + row]           = tf32r(acc[mt][nt][0] + b0v);
            dst[(size_t)(col + 1) * NN + row]     = tf32r(acc[mt][nt][1] + b1v);
            dst[(size_t)col * NN + row + 8]       = tf32r(acc[mt][nt][2] + b0v);
            dst[(size_t)(col + 1) * NN + row + 8] = tf32r(acc[mt][nt][3] + b1v);
        }
    }
}

// ======== fused attention GEMM: BK=64, 3-stage, 512 thr, ldmatrix frags ========
// CTA 128n x 128f, grid (4, 32) = 128 CTAs. 256 iterations over (h, 64-m chunks).
// w = 2^( s_n*t_m * (>=0 ? L2E : 0.3*L2E) + C_n ), C_n = log2(invz_n) - rmax_n*L2E
#define A_CONST 1024                // s_sm[512] + c_sm[512]
#define A_AS (128 * ST2)            // 8704 floats
#define A_STG (2 * A_AS)            // A + B = 17408 floats
#define A_SMEM ((A_CONST + 3 * A_STG) * 4)   // 212992 bytes

__global__ __launch_bounds__(512) void attn_gemm(float* __restrict__ out) {
    extern __shared__ float sm[];
    uint32_t smb = smem_u32(sm);
    float* s_sm = sm;              // [4h][128]
    float* c_sm = sm + 512;        // [4h][128]
    int tid = threadIdx.x, wid = tid >> 5, lane = tid & 31;
    int g = lane >> 2, tg = lane & 3;
    int n0 = blockIdx.y * 128, f0 = blockIdx.x * 128;
    int warp_m = wid & 3, warp_n = wid >> 2;

    {
        int hh = tid >> 7, nl = tid & 127;    // 512 = 4*128
        float iz = g_invz[hh * NN + n0 + nl];
        float rm = g_rmax[hh * NN + n0 + nl];
        s_sm[tid] = g_s[hh * NN + n0 + nl];
        c_sm[tid] = __log2f(iz) - rm * L2E;
    }

    // ldmatrix per-lane offsets (bytes)
    int l7 = lane & 7, lt = lane >> 3;
    uint32_t aoff[2], boff[2];
#pragma unroll
    for (int mt = 0; mt < 2; mt++)
        aoff[mt] = ((warp_m * 32 + mt * 16 + (lt & 1) * 8 + l7) * ST2 + (lt >> 1) * 4) * 4;
#pragma unroll
    for (int nt2 = 0; nt2 < 2; nt2++)
        boff[nt2] = ((warp_n * 32 + nt2 * 16 + (lt >> 1) * 8 + l7) * ST2 + (lt & 1) * 4) * 4;

    float acc[2][4][4];
#pragma unroll
    for (int a = 0; a < 2; a++)
#pragma unroll
        for (int bq = 0; bq < 4; bq++)
#pragma unroll
            for (int c = 0; c < 4; c++) acc[a][bq][c] = 0.f;

    int nloc = tid & 127, kq = tid >> 7;      // weight gen: 16 k's each (kq 0..3)
    int prow = tid >> 2, pseg = tid & 3;      // B copy: 4 x 16B per thread

    auto prod = [&](int c, int s) {
        uint32_t As = smb + (A_CONST + s * A_STG) * 4;
        uint32_t Bs = As + A_AS * 4;
        int h = c >> 6;
        int m0 = (c & 63) << 6;               // 64 m per iteration
        float sv = s_sm[h * 128 + nloc];
        float cn = c_sm[h * 128 + nloc];
        const float4* tp = (const float4*)(g_t + h * NN + m0 + kq * 16);
        float w[16];
#pragma unroll
        for (int q = 0; q < 4; q++) {
            float4 t4 = __ldg(tp + q);
            float tv[4] = {t4.x, t4.y, t4.z, t4.w};
#pragma unroll
            for (int r = 0; r < 4; r++) {
                float sc = sv * tv[r];
                float mult = sc >= 0.f ? L2E : (ALPHA * L2E);
                float y = fmaxf(fmaf(sc, mult, cn), -126.f);
                w[q * 4 + r] = tf32r(fex2(y));
            }
        }
        uint32_t d = As + (nloc * ST2 + kq * 16) * 4;
        asm volatile("st.shared.v4.f32 [%0], {%1,%2,%3,%4};" ::
            "r"(d), "f"(w[0]), "f"(w[1]), "f"(w[2]), "f"(w[3]) : "memory");
        asm volatile("st.shared.v4.f32 [%0], {%1,%2,%3,%4};" ::
            "r"(d + 16), "f"(w[4]), "f"(w[5]), "f"(w[6]), "f"(w[7]) : "memory");
        asm volatile("st.shared.v4.f32 [%0], {%1,%2,%3,%4};" ::
            "r"(d + 32), "f"(w[8]), "f"(w[9]), "f"(w[10]), "f"(w[11]) : "memory");
        asm volatile("st.shared.v4.f32 [%0], {%1,%2,%3,%4};" ::
            "r"(d + 48), "f"(w[12]), "f"(w[13]), "f"(w[14]), "f"(w[15]) : "memory");
        const float* bsrc = g_featsT + (size_t)h * FF * NN
                          + (size_t)(f0 + prow) * NN + m0 + pseg * 16;
        uint32_t bd = Bs + (prow * ST2 + pseg * 16) * 4;
#pragma unroll
        for (int j = 0; j < 4; j++) cpasync16(bd + j * 16, bsrc + j * 4);
    };
    auto domma = [&](int s) {
        uint32_t As = smb + (A_CONST + s * A_STG) * 4;
        uint32_t Bs = As + A_AS * 4;
#pragma unroll
        for (int ks = 0; ks < 8; ks++) {
            uint32_t a0[4], a1[4];
            ldsm4(a0, As + aoff[0] + ks * 32);
            ldsm4(a1, As + aoff[1] + ks * 32);
#pragma unroll
            for (int nt2 = 0; nt2 < 2; nt2++) {
                uint32_t bfr[4];
                ldsm4(bfr, Bs + boff[nt2] + ks * 32);
                mma1688(acc[0][2 * nt2],     a0, bfr[0], bfr[1]);
                mma1688(acc[1][2 * nt2],     a1, bfr[0], bfr[1]);
                mma1688(acc[0][2 * nt2 + 1], a0, bfr[2], bfr[3]);
                mma1688(acc[1][2 * nt2 + 1], a1, bfr[2], bfr[3]);
            }
        }
    };

    const int NIT = HH * (NN / 64);   // 256
    __syncthreads();                  // s_sm/c_sm ready (prod reads them)
    prod(0, 0); cp_commit();
    prod(1, 1); cp_commit();
    cp_wait<1>();
    __syncthreads();
    for (int i = 0; i < NIT; i++) {
        domma(i % 3);
        if (i + 2 < NIT) { prod(i + 2, (i + 2) % 3); cp_commit(); cp_wait<1>(); }
        else if (i + 2 == NIT) cp_wait<0>();
        __syncthreads();
    }

#pragma unroll
    for (int mt = 0; mt < 2; mt++) {
#pragma unroll
        for (int nt = 0; nt < 4; nt++) {
            int row = n0 + warp_m * 32 + mt * 16 + g;
            int col = f0 + warp_n * 32 + nt * 8 + tg * 2;
            float2 v0, v1;
            v0.x = fmaxf(0.25f * acc[mt][nt][0], 0.f);
            v0.y = fmaxf(0.25f * acc[mt][nt][1], 0.f);
            v1.x = fmaxf(0.25f * acc[mt][nt][2], 0.f);
            v1.y = fmaxf(0.25f * acc[mt][nt][3], 0.f);
            *(float2*)(out + (size_t)row * FF + col) = v0;
            *(float2*)(out + (size_t)(row + 8) * FF + col) = v1;
        }
    }
}

// ================= launch =================
extern "C" void kernel_launch(void* const* d_in, const int* in_sizes, int n_in,
                              void* d_out, int out_size)
{
    const float* nodes  = (const float*)d_in[0];
    const float* edges  = (const float*)d_in[1];
    const float* labels = (const float*)d_in[2];
    const float* We     = (const float*)d_in[3];
    const float* be     = (const float*)d_in[4];
    const float* Wm     = (const float*)d_in[5];
    const float* b      = (const float*)d_in[6];
    const float* u      = (const float*)d_in[7];
    const float* v      = (const float*)d_in[8];
    float* out = (float*)d_out;

    static bool attr_done = false;
    if (!attr_done) {
        cudaFuncSetAttribute(feats_gemm, cudaFuncAttributeMaxDynamicSharedMemorySize, F_SMEM);
        cudaFuncSetAttribute(attn_gemm, cudaFuncAttributeMaxDynamicSharedMemorySize, A_SMEM);
        cudaFuncSetAttribute(feats_gemm, cudaFuncAttributePreferredSharedMemoryCarveout, 100);
        cudaFuncSetAttribute(attn_gemm, cudaFuncAttributePreferredSharedMemoryCarveout, 100);
        attr_done = true;
    }

    setup_kernel<<<SETUP_BLOCKS, 256>>>(nodes, edges, labels, Wm, We, b, be, u, v);
    st_kernel<<<HH * NN / 8, 256>>>(nodes);
    minmax_kernel<<<HH, 256>>>();
    feats_gemm<<<dim3(FF / 128, NN / 128, HH), 256, F_SMEM>>>();  // capture slot 4
    z_kernel<<<HH * NN / 8, 256>>>();
    attn_gemm<<<dim3(FF / 128, NN / 128), 512, A_SMEM>>>(out);
}